// round 10
// baseline (speedup 1.0000x reference)
#include <cuda_runtime.h>
#include <cuda_bf16.h>
#include <cuda_fp16.h>
#include <cstdint>

#define MAX_NODES 100000
#define FDIM      128
#define BUCKET_CAP 128

__device__ __half   g_hp[(size_t)MAX_NODES * FDIM];   // h' = h @ W^T (fp16)
__device__ int      g_cnt[MAX_NODES];
__device__ int      g_bucket[(size_t)MAX_NODES * BUCKET_CAP];
__device__ uint32_t g_Wh[FDIM * FDIM / 2];            // W hi, packed bf16x2
__device__ uint32_t g_Wl[FDIM * FDIM / 2];            // W lo, packed bf16x2

// ---------------------------------------------------------------------------
// helpers
// ---------------------------------------------------------------------------
__device__ __forceinline__ uint32_t pack_bf16(float lo, float hi) {
    uint32_t r;
    asm("cvt.rn.bf16x2.f32 %0, %1, %2;" : "=r"(r) : "f"(hi), "f"(lo));
    return r;
}
__device__ __forceinline__ float bf16lo_f(uint32_t p) { return __uint_as_float(p << 16); }
__device__ __forceinline__ float bf16hi_f(uint32_t p) { return __uint_as_float(p & 0xffff0000u); }

__device__ __forceinline__ void mma_bf16(float* d, const uint32_t* a, const uint32_t* bb) {
    asm volatile(
        "mma.sync.aligned.m16n8k16.row.col.f32.bf16.bf16.f32 "
        "{%0,%1,%2,%3}, {%4,%5,%6,%7}, {%8,%9}, {%0,%1,%2,%3};"
        : "+f"(d[0]), "+f"(d[1]), "+f"(d[2]), "+f"(d[3])
        : "r"(a[0]), "r"(a[1]), "r"(a[2]), "r"(a[3]), "r"(bb[0]), "r"(bb[1]));
}

#define LDSM4(r, addr) \
    asm volatile("ldmatrix.sync.aligned.m8n8.x4.shared.b16 {%0,%1,%2,%3}, [%4];" \
        : "=r"((r)[0]), "=r"((r)[1]), "=r"((r)[2]), "=r"((r)[3]) : "r"(addr))

// ---------------------------------------------------------------------------
// Kernel 0: split W into bf16 hi/lo (once, tiny)
// ---------------------------------------------------------------------------
__global__ void wsplit_kernel(const float* __restrict__ W,
                              uint32_t* __restrict__ Wh,
                              uint32_t* __restrict__ Wl) {
    int i = blockIdx.x * blockDim.x + threadIdx.x;
    if (i >= FDIM * FDIM / 2) return;
    float2 w = ((const float2*)W)[i];
    uint32_t hh = pack_bf16(w.x, w.y);
    uint32_t ll = pack_bf16(w.x - bf16lo_f(hh), w.y - bf16hi_f(hh));
    Wh[i] = hh;
    Wl[i] = ll;
}

// ---------------------------------------------------------------------------
// Kernel 1: zero the per-node counters
// ---------------------------------------------------------------------------
__global__ void zero_cnt_kernel(int* __restrict__ cnt, int n) {
    int i = blockIdx.x * blockDim.x + threadIdx.x;
    if (i < n) cnt[i] = 0;
}

// ---------------------------------------------------------------------------
// Kernel 2: histogram + bucket fill. One thread per edge.
// ---------------------------------------------------------------------------
__global__ void bucket_kernel(const int* __restrict__ src,
                              const int* __restrict__ dst,
                              int* __restrict__ cnt,
                              int* __restrict__ bucket,
                              int E) {
    int e = blockIdx.x * blockDim.x + threadIdx.x;
    if (e >= E) return;
    int d = dst[e];
    int pos = atomicAdd(&cnt[d], 1);
    if (pos < BUCKET_CAP)
        bucket[(size_t)d * BUCKET_CAP + pos] = src[e];
}

// ---------------------------------------------------------------------------
// Kernel 3: half-GEMM h'[:, colBase:colBase+64] = h @ W[colBase:+64]^T
// mma.sync bf16 x3, W pre-split, ldmatrix, double-buffered K stages.
// ---------------------------------------------------------------------------
#define KSTG    32
#define STRD    20
#define A_ARR   (128 * STRD)               // 2560 u32
#define W_ARR   (64 * STRD)                // 1280 u32
#define BUF_U32 (2 * A_ARR + 2 * W_ARR)    // 7680 u32
#define SMEM_U32 (2 * BUF_U32)             // 15360 u32 = 61440 B

__global__ void __launch_bounds__(256, 2)
gemm_bf16_half(const float* __restrict__ h,
               const uint32_t* __restrict__ gWh,
               const uint32_t* __restrict__ gWl,
               __half* __restrict__ hp,
               int N, int colBase) {
    extern __shared__ uint32_t sm[];
    uint32_t sbase = (uint32_t)__cvta_generic_to_shared(sm);

    int tid  = threadIdx.x;
    int lane = tid & 31;
    int wid  = tid >> 5;
    int wr   = wid >> 1;          // 0..3: rows wr*32
    int wc   = wid & 1;           // 0..1: cols wc*32 within the 64
    int gid  = lane >> 2;
    int tig  = lane & 3;
    int rowBase = blockIdx.x * FDIM;

    int lrow  = lane & 15;
    int lkoff = (lane >> 4) << 2;

    // A tile coords: 1024 float4 -> 4 iters
    int lr[4], lf[4];
    #pragma unroll
    for (int it = 0; it < 4; ++it) {
        int idx = tid + it * 256;
        lr[it] = idx >> 3;
        lf[it] = idx & 7;
    }
    // W tile coords: 512 uint2 -> 2 iters
    int wrr[2], wf[2];
    #pragma unroll
    for (int it = 0; it < 2; ++it) {
        int idx = tid + it * 256;
        wrr[it] = idx >> 3;        // 0..63
        wf[it]  = idx & 7;
    }

    float acc[2][4][4];
    #pragma unroll
    for (int mt = 0; mt < 2; ++mt)
        #pragma unroll
        for (int nt = 0; nt < 4; ++nt)
            #pragma unroll
            for (int q = 0; q < 4; ++q)
                acc[mt][nt][q] = 0.f;

    float4 av[4];
    uint2  whv[2], wlv[2];

    // prologue: stage 0
    #pragma unroll
    for (int it = 0; it < 4; ++it) {
        int row = rowBase + lr[it];
        av[it] = (row < N) ? *(const float4*)&h[(size_t)row * FDIM + lf[it] * 4]
                           : make_float4(0.f, 0.f, 0.f, 0.f);
    }
    #pragma unroll
    for (int it = 0; it < 2; ++it) {
        int wrow = colBase + wrr[it];
        whv[it] = *(const uint2*)&gWh[wrow * (FDIM / 2) + wf[it] * 2];
        wlv[it] = *(const uint2*)&gWl[wrow * (FDIM / 2) + wf[it] * 2];
    }
    {
        uint32_t* Ah = sm;               uint32_t* Al = sm + A_ARR;
        uint32_t* Wh = sm + 2 * A_ARR;   uint32_t* Wl = Wh + W_ARR;
        #pragma unroll
        for (int it = 0; it < 4; ++it) {
            int off = lr[it] * STRD + lf[it] * 2;
            float4 a = av[it];
            uint32_t h0 = pack_bf16(a.x, a.y), h1 = pack_bf16(a.z, a.w);
            Ah[off] = h0; Ah[off + 1] = h1;
            Al[off]     = pack_bf16(a.x - bf16lo_f(h0), a.y - bf16hi_f(h0));
            Al[off + 1] = pack_bf16(a.z - bf16lo_f(h1), a.w - bf16hi_f(h1));
        }
        #pragma unroll
        for (int it = 0; it < 2; ++it) {
            int off = wrr[it] * STRD + wf[it] * 2;
            Wh[off] = whv[it].x; Wh[off + 1] = whv[it].y;
            Wl[off] = wlv[it].x; Wl[off + 1] = wlv[it].y;
        }
    }
    __syncthreads();

    #pragma unroll
    for (int s = 0; s < 4; ++s) {
        if (s < 3) {
            int kb = (s + 1) * KSTG;
            #pragma unroll
            for (int it = 0; it < 4; ++it) {
                int row = rowBase + lr[it];
                av[it] = (row < N)
                    ? *(const float4*)&h[(size_t)row * FDIM + kb + lf[it] * 4]
                    : make_float4(0.f, 0.f, 0.f, 0.f);
            }
            #pragma unroll
            for (int it = 0; it < 2; ++it) {
                int wrow = colBase + wrr[it];
                whv[it] = *(const uint2*)&gWh[wrow * (FDIM / 2) + (kb >> 1) + wf[it] * 2];
                wlv[it] = *(const uint2*)&gWl[wrow * (FDIM / 2) + (kb >> 1) + wf[it] * 2];
            }
        }

        {
            uint32_t bufB = sbase + (uint32_t)((s & 1) * BUF_U32) * 4u;
            uint32_t AhB = bufB;
            uint32_t AlB = bufB + A_ARR * 4u;
            uint32_t WhB = bufB + 2u * A_ARR * 4u;
            uint32_t WlB = WhB + W_ARR * 4u;

            #pragma unroll
            for (int kk = 0; kk < 2; ++kk) {
                int kp = kk * 8;
                uint32_t ah[2][4], al_[2][4];
                #pragma unroll
                for (int mt = 0; mt < 2; ++mt) {
                    uint32_t off = (uint32_t)(((wr * 32 + mt * 16 + lrow) * STRD) + kp + lkoff) * 4u;
                    LDSM4(ah[mt],  AhB + off);
                    LDSM4(al_[mt], AlB + off);
                }
                #pragma unroll
                for (int p = 0; p < 2; ++p) {
                    uint32_t wh4[4], wl4[4];
                    uint32_t off = (uint32_t)(((wc * 32 + p * 16 + lrow) * STRD) + kp + lkoff) * 4u;
                    LDSM4(wh4, WhB + off);
                    LDSM4(wl4, WlB + off);
                    #pragma unroll
                    for (int hf = 0; hf < 2; ++hf) {
                        int nt = p * 2 + hf;
                        uint32_t bh[2] = { wh4[hf], wh4[2 + hf] };
                        uint32_t bl[2] = { wl4[hf], wl4[2 + hf] };
                        #pragma unroll
                        for (int mt = 0; mt < 2; ++mt) {
                            mma_bf16(acc[mt][nt], ah[mt], bh);
                            mma_bf16(acc[mt][nt], ah[mt], bl);
                            mma_bf16(acc[mt][nt], al_[mt], bh);
                        }
                    }
                }
            }
        }

        if (s < 3) {
            uint32_t* base = sm + (size_t)((s + 1) & 1) * BUF_U32;
            uint32_t* Ah = base;               uint32_t* Al = base + A_ARR;
            uint32_t* Wh = base + 2 * A_ARR;   uint32_t* Wl = Wh + W_ARR;
            #pragma unroll
            for (int it = 0; it < 4; ++it) {
                int off = lr[it] * STRD + lf[it] * 2;
                float4 a = av[it];
                uint32_t h0 = pack_bf16(a.x, a.y), h1 = pack_bf16(a.z, a.w);
                Ah[off] = h0; Ah[off + 1] = h1;
                Al[off]     = pack_bf16(a.x - bf16lo_f(h0), a.y - bf16hi_f(h0));
                Al[off + 1] = pack_bf16(a.z - bf16lo_f(h1), a.w - bf16hi_f(h1));
            }
            #pragma unroll
            for (int it = 0; it < 2; ++it) {
                int off = wrr[it] * STRD + wf[it] * 2;
                Wh[off] = whv[it].x; Wh[off + 1] = whv[it].y;
                Wl[off] = wlv[it].x; Wl[off + 1] = wlv[it].y;
            }
        }
        __syncthreads();
    }

    // store h' half as fp16 pairs
    #pragma unroll
    for (int nt = 0; nt < 4; ++nt) {
        int col = colBase + wc * 32 + nt * 8 + tig * 2;
        #pragma unroll
        for (int mt = 0; mt < 2; ++mt) {
            int r0 = rowBase + wr * 32 + mt * 16;
            int row_a = r0 + gid;
            int row_b = r0 + gid + 8;
            if (row_a < N)
                *(__half2*)&hp[(size_t)row_a * FDIM + col] =
                    __floats2half2_rn(acc[mt][nt][0], acc[mt][nt][1]);
            if (row_b < N)
                *(__half2*)&hp[(size_t)row_b * FDIM + col] =
                    __floats2half2_rn(acc[mt][nt][2], acc[mt][nt][3]);
        }
    }
}

// ---------------------------------------------------------------------------
// Kernel 4: half-gather: accumulate h'[:, colBase:+64] + bias + relu -> out.
// One warp per node; 8 lanes per row-half (uint4 = 8 halves), 4 edges/iter.
// Quarter-warp partials, shfl_xor(8) + shfl_xor(16) reduction.
// ---------------------------------------------------------------------------
__global__ void gather_half_kernel(const uint4* __restrict__ hp4,
                                   const int* __restrict__ cnt,
                                   const int* __restrict__ bucket,
                                   const float4* __restrict__ b4,
                                   float4* __restrict__ out4,
                                   int Nn, int colBase) {
    int warp = (blockIdx.x * blockDim.x + threadIdx.x) >> 5;
    int lane = threadIdx.x & 31;
    if (warp >= Nn) return;
    int qw = lane >> 3;           // quarter-warp 0..3 (edge slot)
    int li = lane & 7;            // owns cols colBase + li*8 .. +7

    int cb4 = colBase >> 3;       // uint4 offset within row

    int deg = cnt[warp];
    if (deg > BUCKET_CAP) deg = BUCKET_CAP;
    const int* bp = bucket + (size_t)warp * BUCKET_CAP;

    int e0 = (lane      < deg) ? bp[lane]      : 0;
    int e1 = (lane + 32 < deg) ? bp[lane + 32] : 0;
    int e2 = (lane + 64 < deg) ? bp[lane + 64] : 0;
    int e3 = (lane + 96 < deg) ? bp[lane + 96] : 0;

    float a0 = 0.f, a1 = 0.f, a2 = 0.f, a3 = 0.f;
    float a4 = 0.f, a5 = 0.f, a6 = 0.f, a7 = 0.f;

    auto accum = [&](uint4 v) {
        float2 f0 = __half22float2(*(__half2*)&v.x);
        float2 f1 = __half22float2(*(__half2*)&v.y);
        float2 f2 = __half22float2(*(__half2*)&v.z);
        float2 f3 = __half22float2(*(__half2*)&v.w);
        a0 += f0.x; a1 += f0.y; a2 += f1.x; a3 += f1.y;
        a4 += f2.x; a5 += f2.y; a6 += f3.x; a7 += f3.y;
    };

    auto chunk = [&](int e, int c) {
        int full = c >> 2;
        #pragma unroll 2
        for (int i = 0; i < full; ++i) {
            int s = __shfl_sync(0xffffffffu, e, 4 * i + qw);
            accum(__ldg(&hp4[(size_t)s * 16 + cb4 + li]));
        }
        int rem = c & 3;
        if (rem) {
            int idx = full * 4 + (qw < rem ? qw : 0);
            int s = __shfl_sync(0xffffffffu, e, idx);
            if (qw < rem)
                accum(__ldg(&hp4[(size_t)s * 16 + cb4 + li]));
        }
    };

    int d0 = deg < 32 ? deg : 32;
    chunk(e0, d0);
    if (deg > 32) {
        int d1 = (deg < 64 ? deg : 64) - 32;
        chunk(e1, d1);
        if (deg > 64) {
            int d2 = (deg < 96 ? deg : 96) - 64;
            chunk(e2, d2);
            if (deg > 96) chunk(e3, deg - 96);
        }
    }

    // reduce across the 4 quarter-warps
    #pragma unroll
    for (int m = 8; m <= 16; m <<= 1) {
        a0 += __shfl_xor_sync(0xffffffffu, a0, m);
        a1 += __shfl_xor_sync(0xffffffffu, a1, m);
        a2 += __shfl_xor_sync(0xffffffffu, a2, m);
        a3 += __shfl_xor_sync(0xffffffffu, a3, m);
        a4 += __shfl_xor_sync(0xffffffffu, a4, m);
        a5 += __shfl_xor_sync(0xffffffffu, a5, m);
        a6 += __shfl_xor_sync(0xffffffffu, a6, m);
        a7 += __shfl_xor_sync(0xffffffffu, a7, m);
    }

    if (qw < 2) {
        int f4 = (colBase >> 2) + li * 2 + qw;
        float4 bb = __ldg(&b4[f4]);
        float4 o = (qw == 0) ? make_float4(a0, a1, a2, a3)
                             : make_float4(a4, a5, a6, a7);
        o.x = fmaxf(o.x + bb.x, 0.f);
        o.y = fmaxf(o.y + bb.y, 0.f);
        o.z = fmaxf(o.z + bb.z, 0.f);
        o.w = fmaxf(o.w + bb.w, 0.f);
        out4[(size_t)warp * (FDIM / 4) + f4] = o;
    }
}

// ---------------------------------------------------------------------------
// Launch: column-split pipeline.
//   s2:   wsplit -> GEMM[0:64] -> ev1 -> GEMM[64:128] -> ev2
//   main: zero+bucket -> wait ev1 -> gather[0:64] -> wait ev2 -> gather[64:128]
// ---------------------------------------------------------------------------
extern "C" void kernel_launch(void* const* d_in, const int* in_sizes, int n_in,
                              void* d_out, int out_size) {
    const float* h   = (const float*)d_in[0];
    const int*   src = (const int*)d_in[1];
    const int*   dst = (const int*)d_in[2];
    const float* W   = (const float*)d_in[3];
    const float* b   = (const float*)d_in[4];
    float*       out = (float*)d_out;

    int N = in_sizes[0] / FDIM;
    int E = in_sizes[1];

    __half*   hp = nullptr;
    int*      cnt = nullptr;
    int*      bucket = nullptr;
    uint32_t* Wh = nullptr;
    uint32_t* Wl = nullptr;
    cudaGetSymbolAddress((void**)&hp, g_hp);
    cudaGetSymbolAddress((void**)&cnt, g_cnt);
    cudaGetSymbolAddress((void**)&bucket, g_bucket);
    cudaGetSymbolAddress((void**)&Wh, g_Wh);
    cudaGetSymbolAddress((void**)&Wl, g_Wl);

    static cudaStream_t s2;
    static cudaEvent_t evFork, ev1, ev2;
    static bool inited = false;
    if (!inited) {
        cudaStreamCreateWithFlags(&s2, cudaStreamNonBlocking);
        cudaEventCreateWithFlags(&evFork, cudaEventDisableTiming);
        cudaEventCreateWithFlags(&ev1, cudaEventDisableTiming);
        cudaEventCreateWithFlags(&ev2, cudaEventDisableTiming);
        cudaFuncSetAttribute(gemm_bf16_half,
                             cudaFuncAttributeMaxDynamicSharedMemorySize,
                             (int)(SMEM_U32 * sizeof(uint32_t)));
        inited = true;
    }

    int gemm_blocks = (N + FDIM - 1) / FDIM;
    int gath_blocks = (N * 32 + 255) / 256;

    cudaEventRecord(evFork, 0);
    cudaStreamWaitEvent(s2, evFork, 0);

    wsplit_kernel<<<(FDIM * FDIM / 2 + 255) / 256, 256, 0, s2>>>(W, Wh, Wl);
    gemm_bf16_half<<<gemm_blocks, 256, SMEM_U32 * sizeof(uint32_t), s2>>>(h, Wh, Wl, hp, N, 0);
    cudaEventRecord(ev1, s2);
    gemm_bf16_half<<<gemm_blocks, 256, SMEM_U32 * sizeof(uint32_t), s2>>>(h, Wh, Wl, hp, N, 64);
    cudaEventRecord(ev2, s2);

    zero_cnt_kernel<<<(N + 255) / 256, 256>>>(cnt, N);
    bucket_kernel<<<(E + 255) / 256, 256>>>(src, dst, cnt, bucket, E);

    cudaStreamWaitEvent(0, ev1, 0);
    gather_half_kernel<<<gath_blocks, 256>>>((const uint4*)hp, cnt, bucket,
                                             (const float4*)b, (float4*)out, N, 0);
    cudaStreamWaitEvent(0, ev2, 0);
    gather_half_kernel<<<gath_blocks, 256>>>((const uint4*)hp, cnt, bucket,
                                             (const float4*)b, (float4*)out, N, 64);
}

// round 11
// speedup vs baseline: 1.0603x; 1.0603x over previous
#include <cuda_runtime.h>
#include <cuda_bf16.h>
#include <cuda_fp16.h>
#include <cstdint>

#define MAX_NODES 100000
#define FDIM      128
#define BUCKET_CAP 128

__device__ __half   g_hp[(size_t)MAX_NODES * FDIM];   // h' = h @ W^T (fp16)
__device__ int      g_cnt[MAX_NODES];                 // zero-init at load; gather re-zeros
__device__ int      g_bucket[(size_t)MAX_NODES * BUCKET_CAP];
__device__ uint32_t g_Wh[FDIM * FDIM / 2];            // W hi, packed bf16x2
__device__ uint32_t g_Wl[FDIM * FDIM / 2];            // W lo, packed bf16x2

// ---------------------------------------------------------------------------
// helpers
// ---------------------------------------------------------------------------
__device__ __forceinline__ uint32_t pack_bf16(float lo, float hi) {
    uint32_t r;
    asm("cvt.rn.bf16x2.f32 %0, %1, %2;" : "=r"(r) : "f"(hi), "f"(lo));
    return r;
}
__device__ __forceinline__ float bf16lo_f(uint32_t p) { return __uint_as_float(p << 16); }
__device__ __forceinline__ float bf16hi_f(uint32_t p) { return __uint_as_float(p & 0xffff0000u); }

__device__ __forceinline__ void mma_bf16(float* d, const uint32_t* a, const uint32_t* bb) {
    asm volatile(
        "mma.sync.aligned.m16n8k16.row.col.f32.bf16.bf16.f32 "
        "{%0,%1,%2,%3}, {%4,%5,%6,%7}, {%8,%9}, {%0,%1,%2,%3};"
        : "+f"(d[0]), "+f"(d[1]), "+f"(d[2]), "+f"(d[3])
        : "r"(a[0]), "r"(a[1]), "r"(a[2]), "r"(a[3]), "r"(bb[0]), "r"(bb[1]));
}

#define LDSM4(r, addr) \
    asm volatile("ldmatrix.sync.aligned.m8n8.x4.shared.b16 {%0,%1,%2,%3}, [%4];" \
        : "=r"((r)[0]), "=r"((r)[1]), "=r"((r)[2]), "=r"((r)[3]) : "r"(addr))

// ---------------------------------------------------------------------------
// Kernel 0: split W into bf16 hi/lo (once per call, tiny)
// ---------------------------------------------------------------------------
__global__ void wsplit_kernel(const float* __restrict__ W,
                              uint32_t* __restrict__ Wh,
                              uint32_t* __restrict__ Wl) {
    int i = blockIdx.x * blockDim.x + threadIdx.x;
    if (i >= FDIM * FDIM / 2) return;
    float2 w = ((const float2*)W)[i];
    uint32_t hh = pack_bf16(w.x, w.y);
    uint32_t ll = pack_bf16(w.x - bf16lo_f(hh), w.y - bf16hi_f(hh));
    Wh[i] = hh;
    Wl[i] = ll;
}

// ---------------------------------------------------------------------------
// Kernel 1: histogram + bucket fill. One thread per edge.
// cnt[] is guaranteed zero on entry (zero-init at load; gather re-zeros).
// ---------------------------------------------------------------------------
__global__ void bucket_kernel(const int* __restrict__ src,
                              const int* __restrict__ dst,
                              int* __restrict__ cnt,
                              int* __restrict__ bucket,
                              int E) {
    int e = blockIdx.x * blockDim.x + threadIdx.x;
    if (e >= E) return;
    int d = dst[e];
    int pos = atomicAdd(&cnt[d], 1);
    if (pos < BUCKET_CAP)
        bucket[(size_t)d * BUCKET_CAP + pos] = src[e];
}

// ---------------------------------------------------------------------------
// Kernel 2: GEMM h' = h @ W^T, mma.sync bf16 x3, W pre-split. h' fp16.
// ---------------------------------------------------------------------------
#define KSTG   32
#define STRD   20
#define ARR    (128 * STRD)
#define SMEM_U32 (2 * 4 * ARR)

__global__ void __launch_bounds__(256, 2)
gemm_bf16_kernel(const float* __restrict__ h,
                 const uint32_t* __restrict__ gWh,
                 const uint32_t* __restrict__ gWl,
                 __half* __restrict__ hp,
                 int N) {
    extern __shared__ uint32_t sm[];
    uint32_t sbase = (uint32_t)__cvta_generic_to_shared(sm);

    int tid  = threadIdx.x;
    int lane = tid & 31;
    int wid  = tid >> 5;
    int wr   = wid >> 1;
    int wc   = wid & 1;
    int gid  = lane >> 2;
    int tig  = lane & 3;
    int rowBase = blockIdx.x * FDIM;

    int lrow  = lane & 15;
    int lkoff = (lane >> 4) << 2;

    int lr[4], lf[4];
    #pragma unroll
    for (int it = 0; it < 4; ++it) {
        int idx = tid + it * 256;
        lr[it] = idx >> 3;
        lf[it] = idx & 7;
    }

    float acc[2][8][4];
    #pragma unroll
    for (int mt = 0; mt < 2; ++mt)
        #pragma unroll
        for (int nt = 0; nt < 8; ++nt)
            #pragma unroll
            for (int q = 0; q < 4; ++q)
                acc[mt][nt][q] = 0.f;

    float4 av[4];
    uint2  whv[4], wlv[4];

    // prologue: stage 0
    #pragma unroll
    for (int it = 0; it < 4; ++it) {
        int row = rowBase + lr[it];
        av[it] = (row < N) ? *(const float4*)&h[(size_t)row * FDIM + lf[it] * 4]
                           : make_float4(0.f, 0.f, 0.f, 0.f);
        whv[it] = *(const uint2*)&gWh[lr[it] * (FDIM / 2) + lf[it] * 2];
        wlv[it] = *(const uint2*)&gWl[lr[it] * (FDIM / 2) + lf[it] * 2];
    }
    {
        uint32_t* Ah = sm;            uint32_t* Al = sm + ARR;
        uint32_t* Wh = sm + 2 * ARR;  uint32_t* Wl = sm + 3 * ARR;
        #pragma unroll
        for (int it = 0; it < 4; ++it) {
            int off = lr[it] * STRD + lf[it] * 2;
            float4 a = av[it];
            uint32_t h0 = pack_bf16(a.x, a.y), h1 = pack_bf16(a.z, a.w);
            Ah[off] = h0; Ah[off + 1] = h1;
            Al[off]     = pack_bf16(a.x - bf16lo_f(h0), a.y - bf16hi_f(h0));
            Al[off + 1] = pack_bf16(a.z - bf16lo_f(h1), a.w - bf16hi_f(h1));
            Wh[off] = whv[it].x; Wh[off + 1] = whv[it].y;
            Wl[off] = wlv[it].x; Wl[off + 1] = wlv[it].y;
        }
    }
    __syncthreads();

    #pragma unroll
    for (int s = 0; s < 4; ++s) {
        if (s < 3) {
            int kb = (s + 1) * KSTG;
            #pragma unroll
            for (int it = 0; it < 4; ++it) {
                int row = rowBase + lr[it];
                av[it] = (row < N)
                    ? *(const float4*)&h[(size_t)row * FDIM + kb + lf[it] * 4]
                    : make_float4(0.f, 0.f, 0.f, 0.f);
                whv[it] = *(const uint2*)&gWh[lr[it] * (FDIM / 2) + (kb >> 1) + lf[it] * 2];
                wlv[it] = *(const uint2*)&gWl[lr[it] * (FDIM / 2) + (kb >> 1) + lf[it] * 2];
            }
        }

        {
            uint32_t bufB = sbase + (uint32_t)((s & 1) * 4 * ARR) * 4u;
            uint32_t AhB = bufB;
            uint32_t AlB = bufB + ARR * 4u;
            uint32_t WhB = bufB + 2u * ARR * 4u;
            uint32_t WlB = bufB + 3u * ARR * 4u;

            #pragma unroll
            for (int kk = 0; kk < 2; ++kk) {
                int kp = kk * 8;
                uint32_t ah[2][4], al_[2][4];
                #pragma unroll
                for (int mt = 0; mt < 2; ++mt) {
                    uint32_t off = (uint32_t)(((wr * 32 + mt * 16 + lrow) * STRD) + kp + lkoff) * 4u;
                    LDSM4(ah[mt],  AhB + off);
                    LDSM4(al_[mt], AlB + off);
                }
                #pragma unroll
                for (int p = 0; p < 4; ++p) {
                    uint32_t wh4[4], wl4[4];
                    uint32_t off = (uint32_t)(((wc * 64 + p * 16 + lrow) * STRD) + kp + lkoff) * 4u;
                    LDSM4(wh4, WhB + off);
                    LDSM4(wl4, WlB + off);
                    #pragma unroll
                    for (int hf = 0; hf < 2; ++hf) {
                        int nt = p * 2 + hf;
                        uint32_t bh[2] = { wh4[hf], wh4[2 + hf] };
                        uint32_t bl[2] = { wl4[hf], wl4[2 + hf] };
                        #pragma unroll
                        for (int mt = 0; mt < 2; ++mt) {
                            mma_bf16(acc[mt][nt], ah[mt], bh);
                            mma_bf16(acc[mt][nt], ah[mt], bl);
                            mma_bf16(acc[mt][nt], al_[mt], bh);
                        }
                    }
                }
            }
        }

        if (s < 3) {
            uint32_t* base = sm + (size_t)((s + 1) & 1) * 4 * ARR;
            uint32_t* Ah = base;            uint32_t* Al = base + ARR;
            uint32_t* Wh = base + 2 * ARR;  uint32_t* Wl = base + 3 * ARR;
            #pragma unroll
            for (int it = 0; it < 4; ++it) {
                int off = lr[it] * STRD + lf[it] * 2;
                float4 a = av[it];
                uint32_t h0 = pack_bf16(a.x, a.y), h1 = pack_bf16(a.z, a.w);
                Ah[off] = h0; Ah[off + 1] = h1;
                Al[off]     = pack_bf16(a.x - bf16lo_f(h0), a.y - bf16hi_f(h0));
                Al[off + 1] = pack_bf16(a.z - bf16lo_f(h1), a.w - bf16hi_f(h1));
                Wh[off] = whv[it].x; Wh[off + 1] = whv[it].y;
                Wl[off] = wlv[it].x; Wl[off + 1] = wlv[it].y;
            }
        }
        __syncthreads();
    }

    // store h' as fp16 pairs
    #pragma unroll
    for (int nt = 0; nt < 8; ++nt) {
        int col = wc * 64 + nt * 8 + tig * 2;
        #pragma unroll
        for (int mt = 0; mt < 2; ++mt) {
            int r0 = rowBase + wr * 32 + mt * 16;
            int row_a = r0 + gid;
            int row_b = r0 + gid + 8;
            if (row_a < N)
                *(__half2*)&hp[(size_t)row_a * FDIM + col] =
                    __floats2half2_rn(acc[mt][nt][0], acc[mt][nt][1]);
            if (row_b < N)
                *(__half2*)&hp[(size_t)row_b * FDIM + col] =
                    __floats2half2_rn(acc[mt][nt][2], acc[mt][nt][3]);
        }
    }
}

// ---------------------------------------------------------------------------
// Kernel 3: gather fp16 h' rows + bias + relu -> fp32 out. One warp per node.
// 16 lanes per row (uint4 = 8 halves), 2 edges per iter; resets cnt to 0.
// ---------------------------------------------------------------------------
__global__ void gather_kernel(const uint4* __restrict__ hp4,
                              int* __restrict__ cnt,
                              const int* __restrict__ bucket,
                              const float4* __restrict__ b4,
                              float4* __restrict__ out4,
                              int Nn) {
    int warp = (blockIdx.x * blockDim.x + threadIdx.x) >> 5;
    int lane = threadIdx.x & 31;
    if (warp >= Nn) return;
    int hw = lane >> 4;
    int li = lane & 15;

    int deg = cnt[warp];
    if (lane == 0) cnt[warp] = 0;      // reset for the next run (replaces zero kernel)
    if (deg > BUCKET_CAP) deg = BUCKET_CAP;
    const int* bp = bucket + (size_t)warp * BUCKET_CAP;

    int e0 = (lane      < deg) ? bp[lane]      : 0;
    int e1 = (lane + 32 < deg) ? bp[lane + 32] : 0;
    int e2 = (lane + 64 < deg) ? bp[lane + 64] : 0;
    int e3 = (lane + 96 < deg) ? bp[lane + 96] : 0;

    float a0 = 0.f, a1 = 0.f, a2 = 0.f, a3 = 0.f;
    float a4 = 0.f, a5 = 0.f, a6 = 0.f, a7 = 0.f;

    auto accum = [&](uint4 v) {
        float2 f0 = __half22float2(*(__half2*)&v.x);
        float2 f1 = __half22float2(*(__half2*)&v.y);
        float2 f2 = __half22float2(*(__half2*)&v.z);
        float2 f3 = __half22float2(*(__half2*)&v.w);
        a0 += f0.x; a1 += f0.y; a2 += f1.x; a3 += f1.y;
        a4 += f2.x; a5 += f2.y; a6 += f3.x; a7 += f3.y;
    };

    auto chunk = [&](int e, int cnt2) {
        int pairs = cnt2 >> 1;
        #pragma unroll 4
        for (int i = 0; i < pairs; ++i) {
            int s = __shfl_sync(0xffffffffu, e, 2 * i + hw);
            accum(__ldg(&hp4[(size_t)s * 16 + li]));
        }
        if (cnt2 & 1) {
            int s = __shfl_sync(0xffffffffu, e, cnt2 - 1);
            if (hw == 0)
                accum(__ldg(&hp4[(size_t)s * 16 + li]));
        }
    };

    int d0 = deg < 32 ? deg : 32;
    chunk(e0, d0);
    if (deg > 32) {
        int d1 = (deg < 64 ? deg : 64) - 32;
        chunk(e1, d1);
        if (deg > 64) {
            int d2 = (deg < 96 ? deg : 96) - 64;
            chunk(e2, d2);
            if (deg > 96) chunk(e3, deg - 96);
        }
    }

    a0 += __shfl_xor_sync(0xffffffffu, a0, 16);
    a1 += __shfl_xor_sync(0xffffffffu, a1, 16);
    a2 += __shfl_xor_sync(0xffffffffu, a2, 16);
    a3 += __shfl_xor_sync(0xffffffffu, a3, 16);
    a4 += __shfl_xor_sync(0xffffffffu, a4, 16);
    a5 += __shfl_xor_sync(0xffffffffu, a5, 16);
    a6 += __shfl_xor_sync(0xffffffffu, a6, 16);
    a7 += __shfl_xor_sync(0xffffffffu, a7, 16);

    float4 bb = __ldg(&b4[li * 2 + hw]);
    float4 o;
    if (hw == 0) o = make_float4(a0, a1, a2, a3);
    else         o = make_float4(a4, a5, a6, a7);
    o.x = fmaxf(o.x + bb.x, 0.f);
    o.y = fmaxf(o.y + bb.y, 0.f);
    o.z = fmaxf(o.z + bb.z, 0.f);
    o.w = fmaxf(o.w + bb.w, 0.f);
    out4[(size_t)warp * (FDIM / 4) + li * 2 + hw] = o;
}

// ---------------------------------------------------------------------------
// Launch: s2 runs wsplit + GEMM; main runs bucket (cnt pre-zeroed); join; gather.
// ---------------------------------------------------------------------------
extern "C" void kernel_launch(void* const* d_in, const int* in_sizes, int n_in,
                              void* d_out, int out_size) {
    const float* h   = (const float*)d_in[0];
    const int*   src = (const int*)d_in[1];
    const int*   dst = (const int*)d_in[2];
    const float* W   = (const float*)d_in[3];
    const float* b   = (const float*)d_in[4];
    float*       out = (float*)d_out;

    int N = in_sizes[0] / FDIM;
    int E = in_sizes[1];

    __half*   hp = nullptr;
    int*      cnt = nullptr;
    int*      bucket = nullptr;
    uint32_t* Wh = nullptr;
    uint32_t* Wl = nullptr;
    cudaGetSymbolAddress((void**)&hp, g_hp);
    cudaGetSymbolAddress((void**)&cnt, g_cnt);
    cudaGetSymbolAddress((void**)&bucket, g_bucket);
    cudaGetSymbolAddress((void**)&Wh, g_Wh);
    cudaGetSymbolAddress((void**)&Wl, g_Wl);

    static cudaStream_t s2;
    static cudaEvent_t evFork, evGemm;
    static bool inited = false;
    if (!inited) {
        cudaStreamCreateWithFlags(&s2, cudaStreamNonBlocking);
        cudaEventCreateWithFlags(&evFork, cudaEventDisableTiming);
        cudaEventCreateWithFlags(&evGemm, cudaEventDisableTiming);
        cudaFuncSetAttribute(gemm_bf16_kernel,
                             cudaFuncAttributeMaxDynamicSharedMemorySize,
                             (int)(SMEM_U32 * sizeof(uint32_t)));
        inited = true;
    }

    cudaEventRecord(evFork, 0);
    cudaStreamWaitEvent(s2, evFork, 0);
    {
        wsplit_kernel<<<(FDIM * FDIM / 2 + 255) / 256, 256, 0, s2>>>(W, Wh, Wl);
        int blocks = (N + FDIM - 1) / FDIM;
        gemm_bf16_kernel<<<blocks, 256, SMEM_U32 * sizeof(uint32_t), s2>>>(h, Wh, Wl, hp, N);
    }
    cudaEventRecord(evGemm, s2);

    bucket_kernel<<<(E + 255) / 256, 256>>>(src, dst, cnt, bucket, E);

    cudaStreamWaitEvent(0, evGemm, 0);
    {
        int blocks = (N * 32 + 255) / 256;
        gather_kernel<<<blocks, 256>>>((const uint4*)hp, cnt, bucket,
                                       (const float4*)b, (float4*)out, N);
    }
}

// round 12
// speedup vs baseline: 1.1389x; 1.0741x over previous
#include <cuda_runtime.h>
#include <cuda_bf16.h>
#include <cuda_fp16.h>
#include <cstdint>

#define MAX_NODES 100000
#define FDIM      128
#define BUCKET_CAP 128

__device__ __half   g_hp[(size_t)MAX_NODES * FDIM];   // h' = h @ W^T (fp16)
__device__ int      g_cnt[MAX_NODES];                 // zero-init at load; gather re-zeros
__device__ int      g_bucket[(size_t)MAX_NODES * BUCKET_CAP];
__device__ uint32_t g_Wh[FDIM * FDIM / 2];            // W hi, packed bf16x2
__device__ uint32_t g_Wl[FDIM * FDIM / 2];            // W lo, packed bf16x2

// ---------------------------------------------------------------------------
// helpers
// ---------------------------------------------------------------------------
__device__ __forceinline__ uint32_t pack_bf16(float lo, float hi) {
    uint32_t r;
    asm("cvt.rn.bf16x2.f32 %0, %1, %2;" : "=r"(r) : "f"(hi), "f"(lo));
    return r;
}
__device__ __forceinline__ float bf16lo_f(uint32_t p) { return __uint_as_float(p << 16); }
__device__ __forceinline__ float bf16hi_f(uint32_t p) { return __uint_as_float(p & 0xffff0000u); }

__device__ __forceinline__ void mma_bf16(float* d, const uint32_t* a, const uint32_t* bb) {
    asm volatile(
        "mma.sync.aligned.m16n8k16.row.col.f32.bf16.bf16.f32 "
        "{%0,%1,%2,%3}, {%4,%5,%6,%7}, {%8,%9}, {%0,%1,%2,%3};"
        : "+f"(d[0]), "+f"(d[1]), "+f"(d[2]), "+f"(d[3])
        : "r"(a[0]), "r"(a[1]), "r"(a[2]), "r"(a[3]), "r"(bb[0]), "r"(bb[1]));
}

#define LDSM4(r, addr) \
    asm volatile("ldmatrix.sync.aligned.m8n8.x4.shared.b16 {%0,%1,%2,%3}, [%4];" \
        : "=r"((r)[0]), "=r"((r)[1]), "=r"((r)[2]), "=r"((r)[3]) : "r"(addr))

// ---------------------------------------------------------------------------
// Kernel 0: split W into bf16 hi/lo (once per call, tiny)
// ---------------------------------------------------------------------------
__global__ void wsplit_kernel(const float* __restrict__ W,
                              uint32_t* __restrict__ Wh,
                              uint32_t* __restrict__ Wl) {
    int i = blockIdx.x * blockDim.x + threadIdx.x;
    if (i >= FDIM * FDIM / 2) return;
    float2 w = ((const float2*)W)[i];
    uint32_t hh = pack_bf16(w.x, w.y);
    uint32_t ll = pack_bf16(w.x - bf16lo_f(hh), w.y - bf16hi_f(hh));
    Wh[i] = hh;
    Wl[i] = ll;
}

// ---------------------------------------------------------------------------
// Kernel 1: histogram + bucket fill. One thread per edge.
// cnt[] is guaranteed zero on entry (zero-init at load; gather re-zeros).
// ---------------------------------------------------------------------------
__global__ void bucket_kernel(const int* __restrict__ src,
                              const int* __restrict__ dst,
                              int* __restrict__ cnt,
                              int* __restrict__ bucket,
                              int E) {
    int e = blockIdx.x * blockDim.x + threadIdx.x;
    if (e >= E) return;
    int d = dst[e];
    int pos = atomicAdd(&cnt[d], 1);
    if (pos < BUCKET_CAP)
        bucket[(size_t)d * BUCKET_CAP + pos] = src[e];
}

// ---------------------------------------------------------------------------
// Kernel 2: GEMM h' = h @ W^T, mma.sync bf16 x3, W pre-split. h' fp16.
// ---------------------------------------------------------------------------
#define KSTG   32
#define STRD   20
#define ARR    (128 * STRD)
#define SMEM_U32 (2 * 4 * ARR)

__global__ void __launch_bounds__(256, 2)
gemm_bf16_kernel(const float* __restrict__ h,
                 const uint32_t* __restrict__ gWh,
                 const uint32_t* __restrict__ gWl,
                 __half* __restrict__ hp,
                 int N) {
    extern __shared__ uint32_t sm[];
    uint32_t sbase = (uint32_t)__cvta_generic_to_shared(sm);

    int tid  = threadIdx.x;
    int lane = tid & 31;
    int wid  = tid >> 5;
    int wr   = wid >> 1;
    int wc   = wid & 1;
    int gid  = lane >> 2;
    int tig  = lane & 3;
    int rowBase = blockIdx.x * FDIM;

    int lrow  = lane & 15;
    int lkoff = (lane >> 4) << 2;

    int lr[4], lf[4];
    #pragma unroll
    for (int it = 0; it < 4; ++it) {
        int idx = tid + it * 256;
        lr[it] = idx >> 3;
        lf[it] = idx & 7;
    }

    float acc[2][8][4];
    #pragma unroll
    for (int mt = 0; mt < 2; ++mt)
        #pragma unroll
        for (int nt = 0; nt < 8; ++nt)
            #pragma unroll
            for (int q = 0; q < 4; ++q)
                acc[mt][nt][q] = 0.f;

    float4 av[4];
    uint2  whv[4], wlv[4];

    // prologue: stage 0
    #pragma unroll
    for (int it = 0; it < 4; ++it) {
        int row = rowBase + lr[it];
        av[it] = (row < N) ? *(const float4*)&h[(size_t)row * FDIM + lf[it] * 4]
                           : make_float4(0.f, 0.f, 0.f, 0.f);
        whv[it] = *(const uint2*)&gWh[lr[it] * (FDIM / 2) + lf[it] * 2];
        wlv[it] = *(const uint2*)&gWl[lr[it] * (FDIM / 2) + lf[it] * 2];
    }
    {
        uint32_t* Ah = sm;            uint32_t* Al = sm + ARR;
        uint32_t* Wh = sm + 2 * ARR;  uint32_t* Wl = sm + 3 * ARR;
        #pragma unroll
        for (int it = 0; it < 4; ++it) {
            int off = lr[it] * STRD + lf[it] * 2;
            float4 a = av[it];
            uint32_t h0 = pack_bf16(a.x, a.y), h1 = pack_bf16(a.z, a.w);
            Ah[off] = h0; Ah[off + 1] = h1;
            Al[off]     = pack_bf16(a.x - bf16lo_f(h0), a.y - bf16hi_f(h0));
            Al[off + 1] = pack_bf16(a.z - bf16lo_f(h1), a.w - bf16hi_f(h1));
            Wh[off] = whv[it].x; Wh[off + 1] = whv[it].y;
            Wl[off] = wlv[it].x; Wl[off + 1] = wlv[it].y;
        }
    }
    __syncthreads();

    #pragma unroll
    for (int s = 0; s < 4; ++s) {
        if (s < 3) {
            int kb = (s + 1) * KSTG;
            #pragma unroll
            for (int it = 0; it < 4; ++it) {
                int row = rowBase + lr[it];
                av[it] = (row < N)
                    ? *(const float4*)&h[(size_t)row * FDIM + kb + lf[it] * 4]
                    : make_float4(0.f, 0.f, 0.f, 0.f);
                whv[it] = *(const uint2*)&gWh[lr[it] * (FDIM / 2) + (kb >> 1) + lf[it] * 2];
                wlv[it] = *(const uint2*)&gWl[lr[it] * (FDIM / 2) + (kb >> 1) + lf[it] * 2];
            }
        }

        {
            uint32_t bufB = sbase + (uint32_t)((s & 1) * 4 * ARR) * 4u;
            uint32_t AhB = bufB;
            uint32_t AlB = bufB + ARR * 4u;
            uint32_t WhB = bufB + 2u * ARR * 4u;
            uint32_t WlB = bufB + 3u * ARR * 4u;

            #pragma unroll
            for (int kk = 0; kk < 2; ++kk) {
                int kp = kk * 8;
                uint32_t ah[2][4], al_[2][4];
                #pragma unroll
                for (int mt = 0; mt < 2; ++mt) {
                    uint32_t off = (uint32_t)(((wr * 32 + mt * 16 + lrow) * STRD) + kp + lkoff) * 4u;
                    LDSM4(ah[mt],  AhB + off);
                    LDSM4(al_[mt], AlB + off);
                }
                #pragma unroll
                for (int p = 0; p < 4; ++p) {
                    uint32_t wh4[4], wl4[4];
                    uint32_t off = (uint32_t)(((wc * 64 + p * 16 + lrow) * STRD) + kp + lkoff) * 4u;
                    LDSM4(wh4, WhB + off);
                    LDSM4(wl4, WlB + off);
                    #pragma unroll
                    for (int hf = 0; hf < 2; ++hf) {
                        int nt = p * 2 + hf;
                        uint32_t bh[2] = { wh4[hf], wh4[2 + hf] };
                        uint32_t bl[2] = { wl4[hf], wl4[2 + hf] };
                        #pragma unroll
                        for (int mt = 0; mt < 2; ++mt) {
                            mma_bf16(acc[mt][nt], ah[mt], bh);
                            mma_bf16(acc[mt][nt], ah[mt], bl);
                            mma_bf16(acc[mt][nt], al_[mt], bh);
                        }
                    }
                }
            }
        }

        if (s < 3) {
            uint32_t* base = sm + (size_t)((s + 1) & 1) * 4 * ARR;
            uint32_t* Ah = base;            uint32_t* Al = base + ARR;
            uint32_t* Wh = base + 2 * ARR;  uint32_t* Wl = base + 3 * ARR;
            #pragma unroll
            for (int it = 0; it < 4; ++it) {
                int off = lr[it] * STRD + lf[it] * 2;
                float4 a = av[it];
                uint32_t h0 = pack_bf16(a.x, a.y), h1 = pack_bf16(a.z, a.w);
                Ah[off] = h0; Ah[off + 1] = h1;
                Al[off]     = pack_bf16(a.x - bf16lo_f(h0), a.y - bf16hi_f(h0));
                Al[off + 1] = pack_bf16(a.z - bf16lo_f(h1), a.w - bf16hi_f(h1));
                Wh[off] = whv[it].x; Wh[off + 1] = whv[it].y;
                Wl[off] = wlv[it].x; Wl[off + 1] = wlv[it].y;
            }
        }
        __syncthreads();
    }

    // store h' as fp16 pairs
    #pragma unroll
    for (int nt = 0; nt < 8; ++nt) {
        int col = wc * 64 + nt * 8 + tig * 2;
        #pragma unroll
        for (int mt = 0; mt < 2; ++mt) {
            int r0 = rowBase + wr * 32 + mt * 16;
            int row_a = r0 + gid;
            int row_b = r0 + gid + 8;
            if (row_a < N)
                *(__half2*)&hp[(size_t)row_a * FDIM + col] =
                    __floats2half2_rn(acc[mt][nt][0], acc[mt][nt][1]);
            if (row_b < N)
                *(__half2*)&hp[(size_t)row_b * FDIM + col] =
                    __floats2half2_rn(acc[mt][nt][2], acc[mt][nt][3]);
        }
    }
}

// ---------------------------------------------------------------------------
// Kernel 3: gather fp16 h' rows + bias + relu -> fp32 out. One warp per node.
// R8 form: 32 lanes per row (uint2 = 4 halves each), 1 edge per iter.
// Also resets cnt[node] = 0 (replaces the zero kernel).
// ---------------------------------------------------------------------------
__global__ void gather_kernel(const uint2* __restrict__ hp2,
                              int* __restrict__ cnt,
                              const int* __restrict__ bucket,
                              const float4* __restrict__ b4,
                              float4* __restrict__ out4,
                              int Nn) {
    int warp = (blockIdx.x * blockDim.x + threadIdx.x) >> 5;
    int lane = threadIdx.x & 31;
    if (warp >= Nn) return;

    int deg = cnt[warp];
    if (lane == 0) cnt[warp] = 0;      // reset for the next run
    if (deg > BUCKET_CAP) deg = BUCKET_CAP;
    const int* bp = bucket + (size_t)warp * BUCKET_CAP;

    int e0 = (lane      < deg) ? bp[lane]      : 0;
    int e1 = (lane + 32 < deg) ? bp[lane + 32] : 0;
    int e2 = (lane + 64 < deg) ? bp[lane + 64] : 0;
    int e3 = (lane + 96 < deg) ? bp[lane + 96] : 0;

    float4 acc = make_float4(0.f, 0.f, 0.f, 0.f);

    int d0 = deg < 32 ? deg : 32;
    #pragma unroll 4
    for (int i = 0; i < d0; ++i) {
        int s = __shfl_sync(0xffffffffu, e0, i);
        uint2 v = __ldg(&hp2[(size_t)s * 32 + lane]);
        float2 f0 = __half22float2(*(__half2*)&v.x);
        float2 f1 = __half22float2(*(__half2*)&v.y);
        acc.x += f0.x; acc.y += f0.y; acc.z += f1.x; acc.w += f1.y;
    }
    if (deg > 32) {
        int d1 = deg < 64 ? deg : 64;
        for (int i = 32; i < d1; ++i) {
            int s = __shfl_sync(0xffffffffu, e1, i - 32);
            uint2 v = __ldg(&hp2[(size_t)s * 32 + lane]);
            float2 f0 = __half22float2(*(__half2*)&v.x);
            float2 f1 = __half22float2(*(__half2*)&v.y);
            acc.x += f0.x; acc.y += f0.y; acc.z += f1.x; acc.w += f1.y;
        }
        int d2 = deg < 96 ? deg : 96;
        for (int i = 64; i < d2; ++i) {
            int s = __shfl_sync(0xffffffffu, e2, i - 64);
            uint2 v = __ldg(&hp2[(size_t)s * 32 + lane]);
            float2 f0 = __half22float2(*(__half2*)&v.x);
            float2 f1 = __half22float2(*(__half2*)&v.y);
            acc.x += f0.x; acc.y += f0.y; acc.z += f1.x; acc.w += f1.y;
        }
        for (int i = 96; i < deg; ++i) {
            int s = __shfl_sync(0xffffffffu, e3, i - 96);
            uint2 v = __ldg(&hp2[(size_t)s * 32 + lane]);
            float2 f0 = __half22float2(*(__half2*)&v.x);
            float2 f1 = __half22float2(*(__half2*)&v.y);
            acc.x += f0.x; acc.y += f0.y; acc.z += f1.x; acc.w += f1.y;
        }
    }

    float4 bb = __ldg(&b4[lane]);
    float4 o;
    o.x = fmaxf(acc.x + bb.x, 0.f);
    o.y = fmaxf(acc.y + bb.y, 0.f);
    o.z = fmaxf(acc.z + bb.z, 0.f);
    o.w = fmaxf(acc.w + bb.w, 0.f);
    out4[(size_t)warp * (FDIM / 4) + lane] = o;
}

// ---------------------------------------------------------------------------
// Launch: s2 runs wsplit + GEMM; main runs bucket (cnt pre-zeroed); join; gather.
// ---------------------------------------------------------------------------
extern "C" void kernel_launch(void* const* d_in, const int* in_sizes, int n_in,
                              void* d_out, int out_size) {
    const float* h   = (const float*)d_in[0];
    const int*   src = (const int*)d_in[1];
    const int*   dst = (const int*)d_in[2];
    const float* W   = (const float*)d_in[3];
    const float* b   = (const float*)d_in[4];
    float*       out = (float*)d_out;

    int N = in_sizes[0] / FDIM;
    int E = in_sizes[1];

    __half*   hp = nullptr;
    int*      cnt = nullptr;
    int*      bucket = nullptr;
    uint32_t* Wh = nullptr;
    uint32_t* Wl = nullptr;
    cudaGetSymbolAddress((void**)&hp, g_hp);
    cudaGetSymbolAddress((void**)&cnt, g_cnt);
    cudaGetSymbolAddress((void**)&bucket, g_bucket);
    cudaGetSymbolAddress((void**)&Wh, g_Wh);
    cudaGetSymbolAddress((void**)&Wl, g_Wl);

    static cudaStream_t s2;
    static cudaEvent_t evFork, evGemm;
    static bool inited = false;
    if (!inited) {
        cudaStreamCreateWithFlags(&s2, cudaStreamNonBlocking);
        cudaEventCreateWithFlags(&evFork, cudaEventDisableTiming);
        cudaEventCreateWithFlags(&evGemm, cudaEventDisableTiming);
        cudaFuncSetAttribute(gemm_bf16_kernel,
                             cudaFuncAttributeMaxDynamicSharedMemorySize,
                             (int)(SMEM_U32 * sizeof(uint32_t)));
        inited = true;
    }

    cudaEventRecord(evFork, 0);
    cudaStreamWaitEvent(s2, evFork, 0);
    {
        wsplit_kernel<<<(FDIM * FDIM / 2 + 255) / 256, 256, 0, s2>>>(W, Wh, Wl);
        int blocks = (N + FDIM - 1) / FDIM;
        gemm_bf16_kernel<<<blocks, 256, SMEM_U32 * sizeof(uint32_t), s2>>>(h, Wh, Wl, hp, N);
    }
    cudaEventRecord(evGemm, s2);

    bucket_kernel<<<(E + 255) / 256, 256>>>(src, dst, cnt, bucket, E);

    cudaStreamWaitEvent(0, evGemm, 0);
    {
        int blocks = (N * 32 + 255) / 256;
        gather_kernel<<<blocks, 256>>>((const uint2*)hp, cnt, bucket,
                                       (const float4*)b, (float4*)out, N);
    }
}

// round 13
// speedup vs baseline: 1.3556x; 1.1903x over previous
#include <cuda_runtime.h>
#include <cuda_bf16.h>
#include <cuda_fp16.h>
#include <cstdint>

#define MAX_NODES 100000
#define FDIM      128
#define BUCKET_CAP 128

__device__ __half   g_hp[(size_t)MAX_NODES * FDIM];   // h' = h @ W^T (fp16)
__device__ int      g_cnt[MAX_NODES];                 // zero-init at load; gather re-zeros
__device__ int      g_bucket[(size_t)MAX_NODES * BUCKET_CAP];
__device__ uint32_t g_Wf[FDIM * FDIM / 2];            // W as packed fp16x2

// ---------------------------------------------------------------------------
// helpers
// ---------------------------------------------------------------------------
__device__ __forceinline__ uint32_t pack_f16(float lo, float hi) {
    __half2 p = __floats2half2_rn(lo, hi);
    return *(uint32_t*)&p;
}

__device__ __forceinline__ void mma_f16(float* d, const uint32_t* a, const uint32_t* bb) {
    asm volatile(
        "mma.sync.aligned.m16n8k16.row.col.f32.f16.f16.f32 "
        "{%0,%1,%2,%3}, {%4,%5,%6,%7}, {%8,%9}, {%0,%1,%2,%3};"
        : "+f"(d[0]), "+f"(d[1]), "+f"(d[2]), "+f"(d[3])
        : "r"(a[0]), "r"(a[1]), "r"(a[2]), "r"(a[3]), "r"(bb[0]), "r"(bb[1]));
}

#define LDSM4(r, addr) \
    asm volatile("ldmatrix.sync.aligned.m8n8.x4.shared.b16 {%0,%1,%2,%3}, [%4];" \
        : "=r"((r)[0]), "=r"((r)[1]), "=r"((r)[2]), "=r"((r)[3]) : "r"(addr))

// ---------------------------------------------------------------------------
// Kernel 0: convert W to fp16 (once per call, tiny)
// ---------------------------------------------------------------------------
__global__ void wconv_kernel(const float* __restrict__ W,
                             uint32_t* __restrict__ Wf) {
    int i = blockIdx.x * blockDim.x + threadIdx.x;
    if (i >= FDIM * FDIM / 2) return;
    float2 w = ((const float2*)W)[i];
    Wf[i] = pack_f16(w.x, w.y);
}

// ---------------------------------------------------------------------------
// Kernel 1: histogram + bucket fill. One thread per edge.
// ---------------------------------------------------------------------------
__global__ void bucket_kernel(const int* __restrict__ src,
                              const int* __restrict__ dst,
                              int* __restrict__ cnt,
                              int* __restrict__ bucket,
                              int E) {
    int e = blockIdx.x * blockDim.x + threadIdx.x;
    if (e >= E) return;
    int d = dst[e];
    int pos = atomicAdd(&cnt[d], 1);
    if (pos < BUCKET_CAP)
        bucket[(size_t)d * BUCKET_CAP + pos] = src[e];
}

// ---------------------------------------------------------------------------
// Kernel 2: GEMM h' = h @ W^T, single-term fp16 mma m16n8k16. h' fp16.
// 128x128 tile per CTA, 256 threads, K in 4 double-buffered stages of 32.
// ---------------------------------------------------------------------------
#define KSTG   32
#define STRD   20
#define ARR    (128 * STRD)        // one operand tile (u32)
#define BUF    (2 * ARR)           // Ah + Wh per buffer
#define SMEM_U32 (2 * BUF)         // 10240 u32 = 40960 B

__global__ void __launch_bounds__(256, 2)
gemm_f16_kernel(const float* __restrict__ h,
                const uint32_t* __restrict__ gWf,
                __half* __restrict__ hp,
                int N) {
    extern __shared__ uint32_t sm[];
    uint32_t sbase = (uint32_t)__cvta_generic_to_shared(sm);

    int tid  = threadIdx.x;
    int lane = tid & 31;
    int wid  = tid >> 5;
    int wr   = wid >> 1;
    int wc   = wid & 1;
    int gid  = lane >> 2;
    int tig  = lane & 3;
    int rowBase = blockIdx.x * FDIM;

    int lrow  = lane & 15;
    int lkoff = (lane >> 4) << 2;

    int lr[4], lf[4];
    #pragma unroll
    for (int it = 0; it < 4; ++it) {
        int idx = tid + it * 256;
        lr[it] = idx >> 3;
        lf[it] = idx & 7;
    }

    float acc[2][8][4];
    #pragma unroll
    for (int mt = 0; mt < 2; ++mt)
        #pragma unroll
        for (int nt = 0; nt < 8; ++nt)
            #pragma unroll
            for (int q = 0; q < 4; ++q)
                acc[mt][nt][q] = 0.f;

    float4 av[4];
    uint2  wv[4];

    // prologue: stage 0
    #pragma unroll
    for (int it = 0; it < 4; ++it) {
        int row = rowBase + lr[it];
        av[it] = (row < N) ? *(const float4*)&h[(size_t)row * FDIM + lf[it] * 4]
                           : make_float4(0.f, 0.f, 0.f, 0.f);
        wv[it] = *(const uint2*)&gWf[lr[it] * (FDIM / 2) + lf[it] * 2];
    }
    {
        uint32_t* Ah = sm;
        uint32_t* Wh = sm + ARR;
        #pragma unroll
        for (int it = 0; it < 4; ++it) {
            int off = lr[it] * STRD + lf[it] * 2;
            float4 a = av[it];
            Ah[off]     = pack_f16(a.x, a.y);
            Ah[off + 1] = pack_f16(a.z, a.w);
            Wh[off] = wv[it].x; Wh[off + 1] = wv[it].y;
        }
    }
    __syncthreads();

    #pragma unroll
    for (int s = 0; s < 4; ++s) {
        if (s < 3) {
            int kb = (s + 1) * KSTG;
            #pragma unroll
            for (int it = 0; it < 4; ++it) {
                int row = rowBase + lr[it];
                av[it] = (row < N)
                    ? *(const float4*)&h[(size_t)row * FDIM + kb + lf[it] * 4]
                    : make_float4(0.f, 0.f, 0.f, 0.f);
                wv[it] = *(const uint2*)&gWf[lr[it] * (FDIM / 2) + (kb >> 1) + lf[it] * 2];
            }
        }

        // MMA on current buffer
        {
            uint32_t bufB = sbase + (uint32_t)((s & 1) * BUF) * 4u;
            uint32_t AhB = bufB;
            uint32_t WhB = bufB + ARR * 4u;

            #pragma unroll
            for (int kk = 0; kk < 2; ++kk) {
                int kp = kk * 8;
                uint32_t ah[2][4];
                #pragma unroll
                for (int mt = 0; mt < 2; ++mt) {
                    uint32_t off = (uint32_t)(((wr * 32 + mt * 16 + lrow) * STRD) + kp + lkoff) * 4u;
                    LDSM4(ah[mt], AhB + off);
                }
                #pragma unroll
                for (int p = 0; p < 4; ++p) {
                    uint32_t wh4[4];
                    uint32_t off = (uint32_t)(((wc * 64 + p * 16 + lrow) * STRD) + kp + lkoff) * 4u;
                    LDSM4(wh4, WhB + off);
                    #pragma unroll
                    for (int hf = 0; hf < 2; ++hf) {
                        int nt = p * 2 + hf;
                        uint32_t bh[2] = { wh4[hf], wh4[2 + hf] };
                        #pragma unroll
                        for (int mt = 0; mt < 2; ++mt)
                            mma_f16(acc[mt][nt], ah[mt], bh);
                    }
                }
            }
        }

        if (s < 3) {
            uint32_t* base = sm + (size_t)((s + 1) & 1) * BUF;
            uint32_t* Ah = base;
            uint32_t* Wh = base + ARR;
            #pragma unroll
            for (int it = 0; it < 4; ++it) {
                int off = lr[it] * STRD + lf[it] * 2;
                float4 a = av[it];
                Ah[off]     = pack_f16(a.x, a.y);
                Ah[off + 1] = pack_f16(a.z, a.w);
                Wh[off] = wv[it].x; Wh[off + 1] = wv[it].y;
            }
        }
        __syncthreads();
    }

    // store h' as fp16 pairs
    #pragma unroll
    for (int nt = 0; nt < 8; ++nt) {
        int col = wc * 64 + nt * 8 + tig * 2;
        #pragma unroll
        for (int mt = 0; mt < 2; ++mt) {
            int r0 = rowBase + wr * 32 + mt * 16;
            int row_a = r0 + gid;
            int row_b = r0 + gid + 8;
            if (row_a < N)
                *(__half2*)&hp[(size_t)row_a * FDIM + col] =
                    __floats2half2_rn(acc[mt][nt][0], acc[mt][nt][1]);
            if (row_b < N)
                *(__half2*)&hp[(size_t)row_b * FDIM + col] =
                    __floats2half2_rn(acc[mt][nt][2], acc[mt][nt][3]);
        }
    }
}

// ---------------------------------------------------------------------------
// Kernel 3: gather fp16 h' rows + bias + relu -> fp32 out. One warp per node.
// 32 lanes per row (uint2 = 4 halves each); resets cnt to 0.
// ---------------------------------------------------------------------------
__global__ void gather_kernel(const uint2* __restrict__ hp2,
                              int* __restrict__ cnt,
                              const int* __restrict__ bucket,
                              const float4* __restrict__ b4,
                              float4* __restrict__ out4,
                              int Nn) {
    int warp = (blockIdx.x * blockDim.x + threadIdx.x) >> 5;
    int lane = threadIdx.x & 31;
    if (warp >= Nn) return;

    int deg = cnt[warp];
    if (lane == 0) cnt[warp] = 0;      // reset for the next run
    if (deg > BUCKET_CAP) deg = BUCKET_CAP;
    const int* bp = bucket + (size_t)warp * BUCKET_CAP;

    int e0 = (lane      < deg) ? bp[lane]      : 0;
    int e1 = (lane + 32 < deg) ? bp[lane + 32] : 0;
    int e2 = (lane + 64 < deg) ? bp[lane + 64] : 0;
    int e3 = (lane + 96 < deg) ? bp[lane + 96] : 0;

    float4 acc = make_float4(0.f, 0.f, 0.f, 0.f);

    int d0 = deg < 32 ? deg : 32;
    #pragma unroll 4
    for (int i = 0; i < d0; ++i) {
        int s = __shfl_sync(0xffffffffu, e0, i);
        uint2 v = __ldg(&hp2[(size_t)s * 32 + lane]);
        float2 f0 = __half22float2(*(__half2*)&v.x);
        float2 f1 = __half22float2(*(__half2*)&v.y);
        acc.x += f0.x; acc.y += f0.y; acc.z += f1.x; acc.w += f1.y;
    }
    if (deg > 32) {
        int d1 = deg < 64 ? deg : 64;
        for (int i = 32; i < d1; ++i) {
            int s = __shfl_sync(0xffffffffu, e1, i - 32);
            uint2 v = __ldg(&hp2[(size_t)s * 32 + lane]);
            float2 f0 = __half22float2(*(__half2*)&v.x);
            float2 f1 = __half22float2(*(__half2*)&v.y);
            acc.x += f0.x; acc.y += f0.y; acc.z += f1.x; acc.w += f1.y;
        }
        int d2 = deg < 96 ? deg : 96;
        for (int i = 64; i < d2; ++i) {
            int s = __shfl_sync(0xffffffffu, e2, i - 64);
            uint2 v = __ldg(&hp2[(size_t)s * 32 + lane]);
            float2 f0 = __half22float2(*(__half2*)&v.x);
            float2 f1 = __half22float2(*(__half2*)&v.y);
            acc.x += f0.x; acc.y += f0.y; acc.z += f1.x; acc.w += f1.y;
        }
        for (int i = 96; i < deg; ++i) {
            int s = __shfl_sync(0xffffffffu, e3, i - 96);
            uint2 v = __ldg(&hp2[(size_t)s * 32 + lane]);
            float2 f0 = __half22float2(*(__half2*)&v.x);
            float2 f1 = __half22float2(*(__half2*)&v.y);
            acc.x += f0.x; acc.y += f0.y; acc.z += f1.x; acc.w += f1.y;
        }
    }

    float4 bb = __ldg(&b4[lane]);
    float4 o;
    o.x = fmaxf(acc.x + bb.x, 0.f);
    o.y = fmaxf(acc.y + bb.y, 0.f);
    o.z = fmaxf(acc.z + bb.z, 0.f);
    o.w = fmaxf(acc.w + bb.w, 0.f);
    out4[(size_t)warp * (FDIM / 4) + lane] = o;
}

// ---------------------------------------------------------------------------
// Launch: s2 runs wconv + GEMM; main runs bucket; join; gather.
// ---------------------------------------------------------------------------
extern "C" void kernel_launch(void* const* d_in, const int* in_sizes, int n_in,
                              void* d_out, int out_size) {
    const float* h   = (const float*)d_in[0];
    const int*   src = (const int*)d_in[1];
    const int*   dst = (const int*)d_in[2];
    const float* W   = (const float*)d_in[3];
    const float* b   = (const float*)d_in[4];
    float*       out = (float*)d_out;

    int N = in_sizes[0] / FDIM;
    int E = in_sizes[1];

    __half*   hp = nullptr;
    int*      cnt = nullptr;
    int*      bucket = nullptr;
    uint32_t* Wf = nullptr;
    cudaGetSymbolAddress((void**)&hp, g_hp);
    cudaGetSymbolAddress((void**)&cnt, g_cnt);
    cudaGetSymbolAddress((void**)&bucket, g_bucket);
    cudaGetSymbolAddress((void**)&Wf, g_Wf);

    static cudaStream_t s2;
    static cudaEvent_t evFork, evGemm;
    static bool inited = false;
    if (!inited) {
        cudaStreamCreateWithFlags(&s2, cudaStreamNonBlocking);
        cudaEventCreateWithFlags(&evFork, cudaEventDisableTiming);
        cudaEventCreateWithFlags(&evGemm, cudaEventDisableTiming);
        cudaFuncSetAttribute(gemm_f16_kernel,
                             cudaFuncAttributeMaxDynamicSharedMemorySize,
                             (int)(SMEM_U32 * sizeof(uint32_t)));
        inited = true;
    }

    cudaEventRecord(evFork, 0);
    cudaStreamWaitEvent(s2, evFork, 0);
    {
        wconv_kernel<<<(FDIM * FDIM / 2 + 255) / 256, 256, 0, s2>>>(W, Wf);
        int blocks = (N + FDIM - 1) / FDIM;
        gemm_f16_kernel<<<blocks, 256, SMEM_U32 * sizeof(uint32_t), s2>>>(h, Wf, hp, N);
    }
    cudaEventRecord(evGemm, s2);

    bucket_kernel<<<(E + 255) / 256, 256>>>(src, dst, cnt, bucket, E);

    cudaStreamWaitEvent(0, evGemm, 0);
    {
        int blocks = (N * 32 + 255) / 256;
        gather_kernel<<<blocks, 256>>>((const uint2*)hp, cnt, bucket,
                                       (const float4*)b, (float4*)out, N);
    }
}

// round 14
// speedup vs baseline: 1.3825x; 1.0198x over previous
#include <cuda_runtime.h>
#include <cuda_bf16.h>
#include <cuda_fp16.h>
#include <cstdint>

#define MAX_NODES 100000
#define FDIM      128
#define BUCKET_CAP 128

__device__ __half   g_hp[(size_t)MAX_NODES * FDIM];   // h' = h @ W^T (fp16)
__device__ int      g_cnt[MAX_NODES];                 // zero-init at load; gather re-zeros
__device__ int      g_bucket[(size_t)MAX_NODES * BUCKET_CAP];
__device__ uint32_t g_Wf[FDIM * FDIM / 2];            // W as packed fp16x2

// ---------------------------------------------------------------------------
// helpers
// ---------------------------------------------------------------------------
__device__ __forceinline__ uint32_t pack_f16(float lo, float hi) {
    __half2 p = __floats2half2_rn(lo, hi);
    return *(uint32_t*)&p;
}

__device__ __forceinline__ void mma_f16(float* d, const uint32_t* a, const uint32_t* bb) {
    asm volatile(
        "mma.sync.aligned.m16n8k16.row.col.f32.f16.f16.f32 "
        "{%0,%1,%2,%3}, {%4,%5,%6,%7}, {%8,%9}, {%0,%1,%2,%3};"
        : "+f"(d[0]), "+f"(d[1]), "+f"(d[2]), "+f"(d[3])
        : "r"(a[0]), "r"(a[1]), "r"(a[2]), "r"(a[3]), "r"(bb[0]), "r"(bb[1]));
}

#define LDSM4(r, addr) \
    asm volatile("ldmatrix.sync.aligned.m8n8.x4.shared.b16 {%0,%1,%2,%3}, [%4];" \
        : "=r"((r)[0]), "=r"((r)[1]), "=r"((r)[2]), "=r"((r)[3]) : "r"(addr))

// ---------------------------------------------------------------------------
// Kernel 0: convert W to fp16 (once per call, tiny)
// ---------------------------------------------------------------------------
__global__ void wconv_kernel(const float* __restrict__ W,
                             uint32_t* __restrict__ Wf) {
    int i = blockIdx.x * blockDim.x + threadIdx.x;
    if (i >= FDIM * FDIM / 2) return;
    float2 w = ((const float2*)W)[i];
    Wf[i] = pack_f16(w.x, w.y);
}

// ---------------------------------------------------------------------------
// Kernel 1: histogram + bucket fill. One thread per edge.
// ---------------------------------------------------------------------------
__global__ void bucket_kernel(const int* __restrict__ src,
                              const int* __restrict__ dst,
                              int* __restrict__ cnt,
                              int* __restrict__ bucket,
                              int E) {
    int e = blockIdx.x * blockDim.x + threadIdx.x;
    if (e >= E) return;
    int d = dst[e];
    int pos = atomicAdd(&cnt[d], 1);
    if (pos < BUCKET_CAP)
        bucket[(size_t)d * BUCKET_CAP + pos] = src[e];
}

// ---------------------------------------------------------------------------
// Kernel 2: GEMM h' = h @ W^T, single-term fp16 mma m16n8k16. h' fp16.
// ---------------------------------------------------------------------------
#define KSTG   32
#define STRD   20
#define ARR    (128 * STRD)
#define BUF    (2 * ARR)
#define SMEM_U32 (2 * BUF)

__global__ void __launch_bounds__(256, 2)
gemm_f16_kernel(const float* __restrict__ h,
                const uint32_t* __restrict__ gWf,
                __half* __restrict__ hp,
                int N) {
    extern __shared__ uint32_t sm[];
    uint32_t sbase = (uint32_t)__cvta_generic_to_shared(sm);

    int tid  = threadIdx.x;
    int lane = tid & 31;
    int wid  = tid >> 5;
    int wr   = wid >> 1;
    int wc   = wid & 1;
    int gid  = lane >> 2;
    int tig  = lane & 3;
    int rowBase = blockIdx.x * FDIM;

    int lrow  = lane & 15;
    int lkoff = (lane >> 4) << 2;

    int lr[4], lf[4];
    #pragma unroll
    for (int it = 0; it < 4; ++it) {
        int idx = tid + it * 256;
        lr[it] = idx >> 3;
        lf[it] = idx & 7;
    }

    float acc[2][8][4];
    #pragma unroll
    for (int mt = 0; mt < 2; ++mt)
        #pragma unroll
        for (int nt = 0; nt < 8; ++nt)
            #pragma unroll
            for (int q = 0; q < 4; ++q)
                acc[mt][nt][q] = 0.f;

    float4 av[4];
    uint2  wv[4];

    #pragma unroll
    for (int it = 0; it < 4; ++it) {
        int row = rowBase + lr[it];
        av[it] = (row < N) ? *(const float4*)&h[(size_t)row * FDIM + lf[it] * 4]
                           : make_float4(0.f, 0.f, 0.f, 0.f);
        wv[it] = *(const uint2*)&gWf[lr[it] * (FDIM / 2) + lf[it] * 2];
    }
    {
        uint32_t* Ah = sm;
        uint32_t* Wh = sm + ARR;
        #pragma unroll
        for (int it = 0; it < 4; ++it) {
            int off = lr[it] * STRD + lf[it] * 2;
            float4 a = av[it];
            Ah[off]     = pack_f16(a.x, a.y);
            Ah[off + 1] = pack_f16(a.z, a.w);
            Wh[off] = wv[it].x; Wh[off + 1] = wv[it].y;
        }
    }
    __syncthreads();

    #pragma unroll
    for (int s = 0; s < 4; ++s) {
        if (s < 3) {
            int kb = (s + 1) * KSTG;
            #pragma unroll
            for (int it = 0; it < 4; ++it) {
                int row = rowBase + lr[it];
                av[it] = (row < N)
                    ? *(const float4*)&h[(size_t)row * FDIM + kb + lf[it] * 4]
                    : make_float4(0.f, 0.f, 0.f, 0.f);
                wv[it] = *(const uint2*)&gWf[lr[it] * (FDIM / 2) + (kb >> 1) + lf[it] * 2];
            }
        }

        {
            uint32_t bufB = sbase + (uint32_t)((s & 1) * BUF) * 4u;
            uint32_t AhB = bufB;
            uint32_t WhB = bufB + ARR * 4u;

            #pragma unroll
            for (int kk = 0; kk < 2; ++kk) {
                int kp = kk * 8;
                uint32_t ah[2][4];
                #pragma unroll
                for (int mt = 0; mt < 2; ++mt) {
                    uint32_t off = (uint32_t)(((wr * 32 + mt * 16 + lrow) * STRD) + kp + lkoff) * 4u;
                    LDSM4(ah[mt], AhB + off);
                }
                #pragma unroll
                for (int p = 0; p < 4; ++p) {
                    uint32_t wh4[4];
                    uint32_t off = (uint32_t)(((wc * 64 + p * 16 + lrow) * STRD) + kp + lkoff) * 4u;
                    LDSM4(wh4, WhB + off);
                    #pragma unroll
                    for (int hf = 0; hf < 2; ++hf) {
                        int nt = p * 2 + hf;
                        uint32_t bh[2] = { wh4[hf], wh4[2 + hf] };
                        #pragma unroll
                        for (int mt = 0; mt < 2; ++mt)
                            mma_f16(acc[mt][nt], ah[mt], bh);
                    }
                }
            }
        }

        if (s < 3) {
            uint32_t* base = sm + (size_t)((s + 1) & 1) * BUF;
            uint32_t* Ah = base;
            uint32_t* Wh = base + ARR;
            #pragma unroll
            for (int it = 0; it < 4; ++it) {
                int off = lr[it] * STRD + lf[it] * 2;
                float4 a = av[it];
                Ah[off]     = pack_f16(a.x, a.y);
                Ah[off + 1] = pack_f16(a.z, a.w);
                Wh[off] = wv[it].x; Wh[off + 1] = wv[it].y;
            }
        }
        __syncthreads();
    }

    #pragma unroll
    for (int nt = 0; nt < 8; ++nt) {
        int col = wc * 64 + nt * 8 + tig * 2;
        #pragma unroll
        for (int mt = 0; mt < 2; ++mt) {
            int r0 = rowBase + wr * 32 + mt * 16;
            int row_a = r0 + gid;
            int row_b = r0 + gid + 8;
            if (row_a < N)
                *(__half2*)&hp[(size_t)row_a * FDIM + col] =
                    __floats2half2_rn(acc[mt][nt][0], acc[mt][nt][1]);
            if (row_b < N)
                *(__half2*)&hp[(size_t)row_b * FDIM + col] =
                    __floats2half2_rn(acc[mt][nt][2], acc[mt][nt][3]);
        }
    }
}

// ---------------------------------------------------------------------------
// Kernel 3: gather fp16 h' rows + bias + relu -> fp32 out. One warp per node.
// 32 lanes per row (uint2); edges processed in PAIRS: fp16 pre-add (__hadd2),
// one fp32 convert+accumulate per pair. Resets cnt to 0.
// ---------------------------------------------------------------------------
__global__ void gather_kernel(const uint2* __restrict__ hp2,
                              int* __restrict__ cnt,
                              const int* __restrict__ bucket,
                              const float4* __restrict__ b4,
                              float4* __restrict__ out4,
                              int Nn) {
    int warp = (blockIdx.x * blockDim.x + threadIdx.x) >> 5;
    int lane = threadIdx.x & 31;
    if (warp >= Nn) return;

    int deg = cnt[warp];
    if (lane == 0) cnt[warp] = 0;      // reset for next run
    if (deg > BUCKET_CAP) deg = BUCKET_CAP;
    const int* bp = bucket + (size_t)warp * BUCKET_CAP;

    int e0 = (lane      < deg) ? bp[lane]      : 0;
    int e1 = (lane + 32 < deg) ? bp[lane + 32] : 0;
    int e2 = (lane + 64 < deg) ? bp[lane + 64] : 0;
    int e3 = (lane + 96 < deg) ? bp[lane + 96] : 0;

    float4 acc = make_float4(0.f, 0.f, 0.f, 0.f);

    auto accum1 = [&](uint2 v) {
        float2 f0 = __half22float2(*(__half2*)&v.x);
        float2 f1 = __half22float2(*(__half2*)&v.y);
        acc.x += f0.x; acc.y += f0.y; acc.z += f1.x; acc.w += f1.y;
    };

    auto chunk = [&](int e, int c) {
        int pairs = c >> 1;
        #pragma unroll 2
        for (int i = 0; i < pairs; ++i) {
            int s0 = __shfl_sync(0xffffffffu, e, 2 * i);
            int s1 = __shfl_sync(0xffffffffu, e, 2 * i + 1);
            uint2 v0 = __ldg(&hp2[(size_t)s0 * 32 + lane]);
            uint2 v1 = __ldg(&hp2[(size_t)s1 * 32 + lane]);
            __half2 p0 = __hadd2(*(__half2*)&v0.x, *(__half2*)&v1.x);
            __half2 p1 = __hadd2(*(__half2*)&v0.y, *(__half2*)&v1.y);
            float2 f0 = __half22float2(p0);
            float2 f1 = __half22float2(p1);
            acc.x += f0.x; acc.y += f0.y; acc.z += f1.x; acc.w += f1.y;
        }
        if (c & 1) {
            int s = __shfl_sync(0xffffffffu, e, c - 1);
            accum1(__ldg(&hp2[(size_t)s * 32 + lane]));
        }
    };

    int d0 = deg < 32 ? deg : 32;
    chunk(e0, d0);
    if (deg > 32) {
        int d1 = (deg < 64 ? deg : 64) - 32;
        chunk(e1, d1);
        if (deg > 64) {
            int d2 = (deg < 96 ? deg : 96) - 64;
            chunk(e2, d2);
            if (deg > 96) chunk(e3, deg - 96);
        }
    }

    float4 bb = __ldg(&b4[lane]);
    float4 o;
    o.x = fmaxf(acc.x + bb.x, 0.f);
    o.y = fmaxf(acc.y + bb.y, 0.f);
    o.z = fmaxf(acc.z + bb.z, 0.f);
    o.w = fmaxf(acc.w + bb.w, 0.f);
    out4[(size_t)warp * (FDIM / 4) + lane] = o;
}

// ---------------------------------------------------------------------------
// Launch: s2 runs wconv + GEMM; main runs bucket; join; gather.
// ---------------------------------------------------------------------------
extern "C" void kernel_launch(void* const* d_in, const int* in_sizes, int n_in,
                              void* d_out, int out_size) {
    const float* h   = (const float*)d_in[0];
    const int*   src = (const int*)d_in[1];
    const int*   dst = (const int*)d_in[2];
    const float* W   = (const float*)d_in[3];
    const float* b   = (const float*)d_in[4];
    float*       out = (float*)d_out;

    int N = in_sizes[0] / FDIM;
    int E = in_sizes[1];

    __half*   hp = nullptr;
    int*      cnt = nullptr;
    int*      bucket = nullptr;
    uint32_t* Wf = nullptr;
    cudaGetSymbolAddress((void**)&hp, g_hp);
    cudaGetSymbolAddress((void**)&cnt, g_cnt);
    cudaGetSymbolAddress((void**)&bucket, g_bucket);
    cudaGetSymbolAddress((void**)&Wf, g_Wf);

    static cudaStream_t s2;
    static cudaEvent_t evFork, evGemm;
    static bool inited = false;
    if (!inited) {
        cudaStreamCreateWithFlags(&s2, cudaStreamNonBlocking);
        cudaEventCreateWithFlags(&evFork, cudaEventDisableTiming);
        cudaEventCreateWithFlags(&evGemm, cudaEventDisableTiming);
        cudaFuncSetAttribute(gemm_f16_kernel,
                             cudaFuncAttributeMaxDynamicSharedMemorySize,
                             (int)(SMEM_U32 * sizeof(uint32_t)));
        inited = true;
    }

    cudaEventRecord(evFork, 0);
    cudaStreamWaitEvent(s2, evFork, 0);
    {
        wconv_kernel<<<(FDIM * FDIM / 2 + 255) / 256, 256, 0, s2>>>(W, Wf);
        int blocks = (N + FDIM - 1) / FDIM;
        gemm_f16_kernel<<<blocks, 256, SMEM_U32 * sizeof(uint32_t), s2>>>(h, Wf, hp, N);
    }
    cudaEventRecord(evGemm, s2);

    bucket_kernel<<<(E + 255) / 256, 256>>>(src, dst, cnt, bucket, E);

    cudaStreamWaitEvent(0, evGemm, 0);
    {
        int blocks = (N * 32 + 255) / 256;
        gather_kernel<<<blocks, 256>>>((const uint2*)hp, cnt, bucket,
                                       (const float4*)b, (float4*)out, N);
    }
}